// round 1
// baseline (speedup 1.0000x reference)
#include <cuda_runtime.h>

// out[mu[k], e] += X1[m1[k], e] * X2[m2[k], e] * mult[k]   for e in [0, N*D)
// M = 9 m-channels, K ~ 100 terms (runtime data), output [9, N*D] float32.
//
// Strategy:
//   setup_kernel: rank-sort the K terms by (mu, m1, m2) so that mu-segments are
//     contiguous (scalar accumulator per segment, no dynamic register indexing),
//     precompute SMEM byte offsets for each term, pack term as one int4.
//   combine_kernel: each block stages a TILE of elements for all 9 channels of
//     X1 and X2 into shared memory (one coalesced global read per byte), then
//     loops mu-segments with a float4 accumulator, reading operands from SMEM.

#define M_CH    9
#define TILE    512      // floats per m-channel per tile (128 float4)
#define THREADS 128
#define MAXK    256

__device__ int4 g_terms[MAXK];     // {off1_bytes, off2_bytes, bits(mult), 0}
__device__ int  g_seg[M_CH + 1];   // segment starts per mu (g_seg[9] == K)

__global__ void setup_kernel(const int* __restrict__ m1,
                             const int* __restrict__ m2,
                             const int* __restrict__ mu,
                             const float* __restrict__ mult,
                             int K)
{
    __shared__ int skey[MAXK];
    int t = threadIdx.x;

    int key = 0x7fffffff;
    if (t < K) key = mu[t] * 81 + m1[t] * 9 + m2[t];
    if (t < MAXK) skey[t] = key;
    __syncthreads();

    if (t < K) {
        // stable rank sort: O(K) per thread, K<=256
        int rank = 0;
        for (int j = 0; j < K; j++) {
            int kj = skey[j];
            rank += (kj < key) | ((kj == key) & (j < t));
        }
        int4 v;
        v.x = m1[t] * (TILE * 4);                     // byte offset into X1 smem region
        v.y = M_CH * TILE * 4 + m2[t] * (TILE * 4);   // byte offset into X2 smem region
        v.z = __float_as_int(mult[t]);
        v.w = 0;
        g_terms[rank] = v;
    }
    if (t <= M_CH) {
        // seg[m] = #{k : mu[k] < m}  (order-independent, no need for sorted mu)
        int c = 0;
        for (int j = 0; j < K; j++) c += (mu[j] < t);
        g_seg[t] = c;
    }
}

__global__ void __launch_bounds__(THREADS)
combine_kernel(const float* __restrict__ X1,
               const float* __restrict__ X2,
               float* __restrict__ out,
               int nd4,   // N*D/4
               int K)
{
    __shared__ float4 sx[2 * M_CH * (TILE / 4)];   // X1 tiles then X2 tiles
    __shared__ int4   sterm[MAXK];
    __shared__ int    sseg[M_CH + 1];

    const int tid   = threadIdx.x;
    const int base4 = blockIdx.x * (TILE / 4);     // float4 element index of tile start

    const float4* __restrict__ X14 = (const float4*)X1;
    const float4* __restrict__ X24 = (const float4*)X2;

    // Stage tiles: 9 channels x TILE floats for each operand, fully coalesced.
#pragma unroll
    for (int m = 0; m < M_CH; m++) {
        sx[m * (TILE / 4) + tid]          = __ldg(&X14[(size_t)m * nd4 + base4 + tid]);
        sx[(M_CH + m) * (TILE / 4) + tid] = __ldg(&X24[(size_t)m * nd4 + base4 + tid]);
    }
    for (int i = tid; i < K; i += THREADS) sterm[i] = g_terms[i];
    if (tid <= M_CH) sseg[tid] = g_seg[tid];
    __syncthreads();

    const char* sb = (const char*)sx + tid * 16;   // this thread's float4 column
    float4* __restrict__ out4 = (float4*)out;

#pragma unroll
    for (int m = 0; m < M_CH; m++) {
        float4 acc = make_float4(0.f, 0.f, 0.f, 0.f);
        const int k0 = sseg[m];
        const int k1 = sseg[m + 1];
        for (int k = k0; k < k1; k++) {
            int4 tm = sterm[k];                              // 1 broadcast LDS.128
            float4 a = *(const float4*)(sb + tm.x);          // LDS.128, conflict-free
            float4 b = *(const float4*)(sb + tm.y);          // LDS.128, conflict-free
            float  c = __int_as_float(tm.z);
            acc.x = fmaf(c * a.x, b.x, acc.x);
            acc.y = fmaf(c * a.y, b.y, acc.y);
            acc.z = fmaf(c * a.z, b.z, acc.z);
            acc.w = fmaf(c * a.w, b.w, acc.w);
        }
        out4[(size_t)m * nd4 + base4 + tid] = acc;           // coalesced STG.128
    }
}

extern "C" void kernel_launch(void* const* d_in, const int* in_sizes, int n_in,
                              void* d_out, int out_size)
{
    const float* X1   = (const float*)d_in[0];
    const float* X2   = (const float*)d_in[1];
    const int*   m1   = (const int*)d_in[2];
    const int*   m2   = (const int*)d_in[3];
    const int*   mu   = (const int*)d_in[4];
    const float* mult = (const float*)d_in[5];
    float*       out  = (float*)d_out;

    const int K  = in_sizes[2];
    const int ND = in_sizes[0] / M_CH;   // N*D
    const int nd4 = ND / 4;

    setup_kernel<<<1, MAXK>>>(m1, m2, mu, mult, K);

    const int nblocks = ND / TILE;       // ND divisible by TILE for this problem
    combine_kernel<<<nblocks, THREADS>>>(X1, X2, out, nd4, K);
}